// round 15
// baseline (speedup 1.0000x reference)
#include <cuda_runtime.h>
#include <cstdint>
#include <cstddef>

#define Bn 128
#define Tn 1024
#define Dn 48
#define Hn 256
#define NBLK 128
#define NTHR 256

typedef unsigned long long ull;

// ---------------- device scratch (no allocations allowed) ----------------
__device__ float g_xT[Tn * Dn * Bn];                  // [t][48][b]
__device__ float g_o0[(size_t)Tn * 2 * Hn * Bn];      // [t][512][b]  layer0 outputs
__device__ float g_gx0[(size_t)Tn * 1024 * Bn];       // x-projection, dir 0 (incl. both biases)
__device__ float g_gx1[(size_t)Tn * 1024 * Bn];       // x-projection, dir 1
__device__ float g_h[2][2][8][Hn * 16];               // [parity][dir][bg][k*16 + b]
__device__ unsigned g_slot[16][8];                    // barrier slots [group][rank]

// ---------------- packed f32x2 helpers ----------------
__device__ __forceinline__ void ffma2(ull& d, ull a, ull b) {
    asm("fma.rn.f32x2 %0, %1, %2, %0;" : "+l"(d) : "l"(a), "l"(b));
}
__device__ __forceinline__ void fadd2(ull& d, ull a) {
    asm("add.rn.f32x2 %0, %0, %1;" : "+l"(d) : "l"(a));
}
__device__ __forceinline__ ull pack2(float a) {
    ull r;
    asm("mov.b64 %0, {%1, %1};" : "=l"(r) : "f"(a));
    return r;
}
__device__ __forceinline__ void unpack2(ull v, float& lo, float& hi) {
    asm("mov.b64 {%0, %1}, %2;" : "=f"(lo), "=f"(hi) : "l"(v));
}

// ---------------- cp.async helpers ----------------
__device__ __forceinline__ void cp_async16(void* smem_dst, const void* gsrc) {
    unsigned dst = (unsigned)__cvta_generic_to_shared(smem_dst);
    asm volatile("cp.async.cg.shared.global [%0], [%1], 16;" :: "r"(dst), "l"(gsrc) : "memory");
}
__device__ __forceinline__ void cp_commit() { asm volatile("cp.async.commit_group;" ::: "memory"); }
template<int N>
__device__ __forceinline__ void cp_wait() {
    asm volatile("cp.async.wait_group %0;" :: "n"(N) : "memory");
}

// ---------------- acquire/release ----------------
__device__ __forceinline__ void st_release(unsigned* p, unsigned v) {
    asm volatile("st.release.gpu.u32 [%0], %1;" :: "l"(p), "r"(v) : "memory");
}
__device__ __forceinline__ unsigned ld_acquire(unsigned* p) {
    unsigned v;
    asm volatile("ld.acquire.gpu.u32 %0, [%1];" : "=r"(v) : "l"(p) : "memory");
    return v;
}

// ---------------- transpose x ----------------
__global__ void transpose_x_kernel(const float* __restrict__ x) {
    int idx = blockIdx.x * blockDim.x + threadIdx.x;
    if (idx >= Tn * Dn * Bn) return;
    int b = idx & (Bn - 1);
    int rem = idx >> 7;
    int d = rem % Dn;
    int t = rem / Dn;
    g_xT[idx] = x[((size_t)b * Tn + t) * Dn + d];
}

__device__ __forceinline__ float sigmoidf_(float v) { return 1.0f / (1.0f + __expf(-v)); }

// ================= x-projection GEMM (r14-proven: conflict-free padded s_x) =================
#define XP_SW_STRIDE 132
#define XP_XPAD(CH) ((CH) * 16 + 4)
template<int K, int CHUNK, bool SRC_O0>
__global__ void __launch_bounds__(128) xproj_kernel(
    const float* __restrict__ Wf, const float* __restrict__ Wb,
    const float* __restrict__ bihf, const float* __restrict__ bhhf,
    const float* __restrict__ bihb, const float* __restrict__ bhhb)
{
    __shared__ float s_x[8 * XP_XPAD(CHUNK)];
    __shared__ float s_w[CHUNK * XP_SW_STRIDE];

    const float* xin = SRC_O0 ? g_o0 : g_xT;     // device-side symbol resolution (ATS bug fix)

    const int t   = blockIdx.x;
    const int rt  = blockIdx.y;
    const int dir = blockIdx.z;
    const int tid = threadIdx.x;
    const int rg  = tid >> 3;              // 0..15, 8 rows each
    const int bgp = tid & 7;               // 0..7, 16 batches each

    const float* W   = dir ? Wb   : Wf;
    const float* bih = dir ? bihb : bihf;
    const float* bhh = dir ? bhhb : bhhf;
    float* gout = dir ? g_gx1 : g_gx0;

    ull acc[8][8];
#pragma unroll
    for (int u = 0; u < 8; ++u)
#pragma unroll
        for (int p = 0; p < 8; ++p) acc[u][p] = 0ull;

    const int wrow = rt * 128 + tid;
    for (int kc = 0; kc < K; kc += CHUNK) {
        const float* xsrc = xin + ((size_t)t * K + kc) * Bn;
        for (int i = tid; i < CHUNK * 32; i += 128) {
            int kk = i >> 5;
            int b4 = (i & 31) * 4;
            float4 v = *(const float4*)(xsrc + kk * Bn + b4);
            *(float4*)(s_x + (b4 >> 4) * XP_XPAD(CHUNK) + kk * 16 + (b4 & 15)) = v;
        }
        {
            const float* wsrc = W + (size_t)wrow * K + kc;
#pragma unroll
            for (int k4 = 0; k4 < CHUNK / 4; ++k4) {
                float4 v = *(const float4*)(wsrc + k4 * 4);
                s_w[(k4 * 4 + 0) * XP_SW_STRIDE + tid] = v.x;
                s_w[(k4 * 4 + 1) * XP_SW_STRIDE + tid] = v.y;
                s_w[(k4 * 4 + 2) * XP_SW_STRIDE + tid] = v.z;
                s_w[(k4 * 4 + 3) * XP_SW_STRIDE + tid] = v.w;
            }
        }
        __syncthreads();

#pragma unroll 2
        for (int kk = 0; kk < CHUNK; ++kk) {
            float4 wa = *(const float4*)(s_w + kk * XP_SW_STRIDE + rg * 8);
            float4 wb = *(const float4*)(s_w + kk * XP_SW_STRIDE + rg * 8 + 4);
            ull w0 = pack2(wa.x), w1 = pack2(wa.y), w2 = pack2(wa.z), w3 = pack2(wa.w);
            ull w4 = pack2(wb.x), w5 = pack2(wb.y), w6 = pack2(wb.z), w7 = pack2(wb.w);
            const float* xp = s_x + bgp * XP_XPAD(CHUNK) + kk * 16;
            ulonglong2 x0 = *(const ulonglong2*)(xp);
            ulonglong2 x1 = *(const ulonglong2*)(xp + 4);
            ulonglong2 x2 = *(const ulonglong2*)(xp + 8);
            ulonglong2 x3 = *(const ulonglong2*)(xp + 12);
            ull xv[8] = {x0.x, x0.y, x1.x, x1.y, x2.x, x2.y, x3.x, x3.y};
#define ROW(U, WV) \
            ffma2(acc[U][0], WV, xv[0]); ffma2(acc[U][1], WV, xv[1]); \
            ffma2(acc[U][2], WV, xv[2]); ffma2(acc[U][3], WV, xv[3]); \
            ffma2(acc[U][4], WV, xv[4]); ffma2(acc[U][5], WV, xv[5]); \
            ffma2(acc[U][6], WV, xv[6]); ffma2(acc[U][7], WV, xv[7]);
            ROW(0, w0) ROW(1, w1) ROW(2, w2) ROW(3, w3)
            ROW(4, w4) ROW(5, w5) ROW(6, w6) ROW(7, w7)
#undef ROW
        }
        __syncthreads();
    }

#pragma unroll
    for (int u = 0; u < 8; ++u) {
        int grow = rt * 128 + rg * 8 + u;
        ull bb = pack2(bih[grow] + bhh[grow]);
        float* dst = gout + ((size_t)t * 1024 + grow) * Bn + bgp * 16;
#pragma unroll
        for (int p = 0; p < 8; ++p) fadd2(acc[u][p], bb);
        *(ulonglong2*)(dst)      = make_ulonglong2(acc[u][0], acc[u][1]);
        *(ulonglong2*)(dst + 4)  = make_ulonglong2(acc[u][2], acc[u][3]);
        *(ulonglong2*)(dst + 8)  = make_ulonglong2(acc[u][4], acc[u][5]);
        *(ulonglong2*)(dst + 12) = make_ulonglong2(acc[u][6], acc[u][7]);
    }
}

// ================= recurrent phase: register-resident gates =================
// 128 blocks: dir = bid>>6, bg = (bid>>3)&7 (16 batches), hs = bid&7 (32 units)
// 256 threads: u = tid>>3 (unit 0..31), p = tid&7 (batch pair: b = 2p, 2p+1)
// Thread computes all 4 gates x 2 batches over full K=256, gates stay in regs:
//   acc pairs (i,f) and (g,o) per batch -> 4 f32x2 accumulators.
// s_w permuted: s_w[k*128 + u*4 + g] so one LDS.128 gives all 4 gate weights,
// naturally packed as (i,f),(g,o). h staged in 4 k-quarters with staggered waits.
// smem (floats): s_w [256][128]; s_h [256][16]; s_gx [128][16]  = 155,648 B
#define RC_SW_FLOATS (256 * 128)
#define RC_SH_OFF    RC_SW_FLOATS
#define RC_SGX_OFF   (RC_SH_OFF + 256 * 16)
#define RC_SMEM_FLOATS (RC_SGX_OFF + 128 * 16)

template<bool L0P>
__global__ void __launch_bounds__(NTHR, 1) rec_kernel(
    const float* __restrict__ Whhf, const float* __restrict__ Whhb,
    const int* __restrict__ lengths)
{
    extern __shared__ float sm[];
    float* s_w  = sm;
    float* s_h  = sm + RC_SH_OFF;
    float* s_gx = sm + RC_SGX_OFF;

    const int tid = threadIdx.x;
    const int dir = blockIdx.x >> 6;
    const int bg  = (blockIdx.x >> 3) & 7;
    const int hs  = blockIdx.x & 7;
    const int grp = blockIdx.x >> 3;
    const int u   = tid >> 3;          // unit 0..31
    const int p   = tid & 7;           // batch pair 0..7

    const float* Whh = dir ? Whhb : Whhf;
    const float* gxb = dir ? g_gx1 : g_gx0;

    // ---- stage Whh slice, permuted: s_w[k*128 + (r&31)*4 + (r>>5)] = Whh[grow(r)][k] ----
    for (int i = tid; i < 128 * 64; i += NTHR) {
        int r  = i & 127;                       // local gate row (gate = r>>5, unit = r&31)
        int k4 = (i >> 7) * 4;
        int grow = (r >> 5) * Hn + hs * 32 + (r & 31);
        int pos  = (r & 31) * 4 + (r >> 5);
        float4 v = *(const float4*)(Whh + (size_t)grow * Hn + k4);
        s_w[(k4 + 0) * 128 + pos] = v.x;
        s_w[(k4 + 1) * 128 + pos] = v.y;
        s_w[(k4 + 2) * 128 + pos] = v.z;
        s_w[(k4 + 3) * 128 + pos] = v.w;
    }

    // ---- zero own g_h slice, both parities ----
#pragma unroll
    for (int i = 0; i < 2; ++i) {
        int c = tid + i * NTHR;
        __stcg(&g_h[0][dir][bg][hs * 512 + c], 0.0f);
        __stcg(&g_h[1][dir][bg][hs * 512 + c], 0.0f);
    }

    float c0 = 0.f, c1 = 0.f, h0 = 0.f, h1 = 0.f;
    const int len0 = lengths[bg * 16 + 2 * p];
    const int len1 = lengths[bg * 16 + 2 * p + 1];

    const unsigned base = ld_acquire(&g_slot[grp][hs]);

    // ---- prefetch gx for step 0 ----
    {
        int t0 = dir ? (Tn - 1) : 0;
        const float* gxrow = gxb + (size_t)t0 * 1024 * Bn;
        for (int i = tid; i < 512; i += NTHR) {
            int r = i >> 2, b4 = (i & 3) * 4;
            int grow = (r >> 5) * Hn + hs * 32 + (r & 31);
            cp_async16(s_gx + r * 16 + b4, gxrow + (size_t)grow * Bn + bg * 16 + b4);
        }
        cp_commit();
    }

    // ---- prologue barrier: all blocks' g_h zeroing visible ----
    __syncthreads();
    if (tid == 0) st_release(&g_slot[grp][hs], base + 1);
    if (tid < 8) { while (ld_acquire(&g_slot[grp][tid]) < base + 1) {} }
    __syncthreads();

    for (int s = 0; s < Tn; ++s) {
        const int t = dir ? (Tn - 1 - s) : s;

        // ---- stage h in 4 k-quarters (4 KB each), separate commit groups ----
        {
            const float* hsrc = &g_h[s & 1][dir][bg][0];
#pragma unroll
            for (int q = 0; q < 4; ++q) {
                cp_async16(s_h + q * 1024 + tid * 4, hsrc + q * 1024 + tid * 4);
                cp_commit();
            }
        }

        ull a_if0 = 0ull, a_go0 = 0ull, a_if1 = 0ull, a_go1 = 0ull;

#define QUARTER(Q, WAITN)                                                   \
        {                                                                   \
            cp_wait<WAITN>();                                               \
            __syncthreads();                                                \
            const float* wq = s_w + (Q * 64) * 128 + u * 4;                 \
            const float* hq = s_h + (Q * 64) * 16 + p * 2;                  \
            _Pragma("unroll 8")                                             \
            for (int kk = 0; kk < 64; ++kk) {                               \
                ulonglong2 wv = *(const ulonglong2*)(wq + kk * 128);        \
                float2 h2 = *(const float2*)(hq + kk * 16);                 \
                ull hb0 = pack2(h2.x);                                      \
                ull hb1 = pack2(h2.y);                                      \
                ffma2(a_if0, wv.x, hb0); ffma2(a_go0, wv.y, hb0);           \
                ffma2(a_if1, wv.x, hb1); ffma2(a_go1, wv.y, hb1);           \
            }                                                               \
        }
        QUARTER(0, 3)
        QUARTER(1, 2)
        QUARTER(2, 1)
        QUARTER(3, 0)
#undef QUARTER

        // ---- pointwise: 2 cells (u, 2p), (u, 2p+1); gx added here ----
        {
            int b0i = 2 * p, b1i = 2 * p + 1;
            float gxi0 = s_gx[(u)      * 16 + b0i], gxi1 = s_gx[(u)      * 16 + b1i];
            float gxf0 = s_gx[(32 + u) * 16 + b0i], gxf1 = s_gx[(32 + u) * 16 + b1i];
            float gxg0 = s_gx[(64 + u) * 16 + b0i], gxg1 = s_gx[(64 + u) * 16 + b1i];
            float gxo0 = s_gx[(96 + u) * 16 + b0i], gxo1 = s_gx[(96 + u) * 16 + b1i];

            float ai0, af0, ag0, ao0, ai1, af1, ag1, ao1;
            unpack2(a_if0, ai0, af0);
            unpack2(a_go0, ag0, ao0);
            unpack2(a_if1, ai1, af1);
            unpack2(a_go1, ag1, ao1);

            float ig0 = sigmoidf_(gxi0 + ai0), fg0 = sigmoidf_(gxf0 + af0);
            float gg0 = tanhf(gxg0 + ag0),     og0 = sigmoidf_(gxo0 + ao0);
            float ig1 = sigmoidf_(gxi1 + ai1), fg1 = sigmoidf_(gxf1 + af1);
            float gg1 = tanhf(gxg1 + ag1),     og1 = sigmoidf_(gxo1 + ao1);

            float cn0 = fg0 * c0 + ig0 * gg0;
            float hn0 = og0 * tanhf(cn0);
            float cn1 = fg1 * c1 + ig1 * gg1;
            float hn1 = og1 * tanhf(cn1);
            bool m0 = (t < len0), m1 = (t < len1);
            c0 = m0 ? cn0 : c0;  h0 = m0 ? hn0 : h0;
            c1 = m1 ? cn1 : c1;  h1 = m1 ? hn1 : h1;

            float2 hv = make_float2(h0, h1);
            __stcg((float2*)&g_h[(s + 1) & 1][dir][bg][hs * 512 + u * 16 + 2 * p], hv);
            if (L0P) {
                float2 ov = make_float2(m0 ? hn0 : 0.0f, m1 ? hn1 : 0.0f);
                __stcg((float2*)&g_o0[((size_t)t * 512 + dir * Hn + hs * 32 + u) * Bn
                                      + bg * 16 + 2 * p], ov);
            }
        }

        // ---- barrier (gx prefetch for s+1 overlaps the spin) ----
        __syncthreads();
        if (s + 1 < Tn) {
            int tn = dir ? (Tn - 2 - s) : (s + 1);
            const float* gxrow = gxb + (size_t)tn * 1024 * Bn;
            for (int i = tid; i < 512; i += NTHR) {
                int r = i >> 2, b4 = (i & 3) * 4;
                int grow = (r >> 5) * Hn + hs * 32 + (r & 31);
                cp_async16(s_gx + r * 16 + b4, gxrow + (size_t)grow * Bn + bg * 16 + b4);
            }
            cp_commit();
        }
        if (tid == 0) st_release(&g_slot[grp][hs], base + 2 + s);
        if (tid < 8) { while (ld_acquire(&g_slot[grp][tid]) < base + 2 + (unsigned)s) {} }
        __syncthreads();
    }
}

// ---------------- FC head ----------------
__global__ void head_kernel(const float* __restrict__ fc1_w, const float* __restrict__ fc1_b,
                            const float* __restrict__ fc2_w, const float* __restrict__ fc2_b,
                            float* __restrict__ out)
{
    __shared__ float s_h[2 * Hn];
    __shared__ float s_r[256];
    int b = blockIdx.x;
    int tid = threadIdx.x;
    int bg = b >> 4, bl = b & 15;
    // final L1 states: 1024 steps -> parity 0
    for (int k = tid; k < 2 * Hn; k += 256) {
        int d = k >> 8;
        int j = k & (Hn - 1);
        s_h[k] = g_h[0][d][bg][j * 16 + bl];
    }
    __syncthreads();

    const float* wr = fc1_w + (size_t)tid * 2 * Hn;
    float sum = fc1_b[tid];
#pragma unroll 8
    for (int k = 0; k < 2 * Hn; ++k) sum += wr[k] * s_h[k];
    s_r[tid] = fmaxf(sum, 0.0f) * fc2_w[tid];
    __syncthreads();
    for (int st = 128; st > 0; st >>= 1) {
        if (tid < st) s_r[tid] += s_r[tid + st];
        __syncthreads();
    }
    if (tid == 0) out[b] = s_r[0] + fc2_b[0];
}

// ---------------- launch ----------------
extern "C" void kernel_launch(void* const* d_in, const int* in_sizes, int n_in,
                              void* d_out, int out_size)
{
    const float* x        = (const float*)d_in[0];
    const int*   lengths  = (const int*)  d_in[1];
    const float* w_ih_l0f = (const float*)d_in[2];
    const float* w_hh_l0f = (const float*)d_in[3];
    const float* b_ih_l0f = (const float*)d_in[4];
    const float* b_hh_l0f = (const float*)d_in[5];
    const float* w_ih_l0b = (const float*)d_in[6];
    const float* w_hh_l0b = (const float*)d_in[7];
    const float* b_ih_l0b = (const float*)d_in[8];
    const float* b_hh_l0b = (const float*)d_in[9];
    const float* w_ih_l1f = (const float*)d_in[10];
    const float* w_hh_l1f = (const float*)d_in[11];
    const float* b_ih_l1f = (const float*)d_in[12];
    const float* b_hh_l1f = (const float*)d_in[13];
    const float* w_ih_l1b = (const float*)d_in[14];
    const float* w_hh_l1b = (const float*)d_in[15];
    const float* b_ih_l1b = (const float*)d_in[16];
    const float* b_hh_l1b = (const float*)d_in[17];
    const float* fc1_w    = (const float*)d_in[18];
    const float* fc1_b    = (const float*)d_in[19];
    const float* fc2_w    = (const float*)d_in[20];
    const float* fc2_b    = (const float*)d_in[21];

    const int rec_smem = RC_SMEM_FLOATS * (int)sizeof(float);   // 155,648 B

    cudaFuncSetAttribute((const void*)rec_kernel<true>,
                         cudaFuncAttributeMaxDynamicSharedMemorySize, rec_smem);
    cudaFuncSetAttribute((const void*)rec_kernel<false>,
                         cudaFuncAttributeMaxDynamicSharedMemorySize, rec_smem);

    transpose_x_kernel<<<(Tn * Dn * Bn + 255) / 256, 256>>>(x);

    dim3 xpgrid(Tn, 8, 2);

    // layer-0 x-projection: g_xT -> g_gx
    xproj_kernel<48, 16, false><<<xpgrid, 128>>>(
        w_ih_l0f, w_ih_l0b, b_ih_l0f, b_hh_l0f, b_ih_l0b, b_hh_l0b);

    // layer-0 recurrence (h-only, consumes gx, writes g_o0)
    rec_kernel<true><<<NBLK, NTHR, rec_smem>>>(w_hh_l0f, w_hh_l0b, lengths);

    // layer-1 x-projection: g_o0 -> g_gx
    xproj_kernel<512, 32, true><<<xpgrid, 128>>>(
        w_ih_l1f, w_ih_l1b, b_ih_l1f, b_hh_l1f, b_ih_l1b, b_hh_l1b);

    // layer-1 recurrence (h-only, consumes gx)
    rec_kernel<false><<<NBLK, NTHR, rec_smem>>>(w_hh_l1f, w_hh_l1b, lengths);

    head_kernel<<<Bn, 256>>>(fc1_w, fc1_b, fc2_w, fc2_b, (float*)d_out);
}